// round 13
// baseline (speedup 1.0000x reference)
#include <cuda_runtime.h>
#include <stdint.h>

#define NB 8
#define HH 96
#define WW 96
#define HW 9216
#define CHW 147456
#define NPIX 73728
#define HID 128
#define NSTEPS 64
#define W1COLS 176

#define TIW 32
#define TIH 16
#define HLW 34
#define HLH 18
#define TSZ 612          // 34*18 tile incl 1-px halo
#define H2W 36
#define NBLK 144         // 8 batches * (3x6 tiles)

// smem byte offsets
#define SM_WZ 0          // float[32*128]      16384
#define SM_W2 16384      // ull[64*16]          8192
#define SM_BI 24576      // ull[64]              512
#define SM_BT 25088      // u32[64*16]          4096
#define SM_MX 29184      // float[16*612]      39168
#define SM_AL 68352      // float[612]          2448
#define SM_A2 70800      // float[720]          2880
#define SM_PL 73680      // uchar[512]           512
#define SM_KY 74192      // u32[128]             512
#define SM_ZZ 74704      // ulonglong2[32*256] 131072
#define SM_TOT 205776

typedef unsigned long long ull;

// Scratch (allocation-free)
__device__ float g_R[2][NB * CHW];
__device__ unsigned char g_PL[2][NPIX];
__device__ unsigned g_flagpad[NBLK * 32];   // per-block step flag, 128B stride (monotonic across replays)

// ---------------- f32x2 helpers ----------------
__device__ __forceinline__ ull fma2(ull a, ull b, ull c) {
  ull d;
  asm("fma.rn.f32x2 %0, %1, %2, %3;" : "=l"(d) : "l"(a), "l"(b), "l"(c));
  return d;
}
__device__ __forceinline__ ull pack2(float lo, float hi) {
  ull r;
  asm("mov.b64 %0, {%1, %2};" : "=l"(r) : "f"(lo), "f"(hi));
  return r;
}
__device__ __forceinline__ float2 unpack2(ull v) {
  float2 f;
  asm("mov.b64 {%0, %1}, %2;" : "=f"(f.x), "=f"(f.y) : "l"(v));
  return f;
}

// ---------------- Threefry-2x32 (matches JAX partitionable) ----------------
__device__ __forceinline__ void tf2x32(uint32_t k0, uint32_t k1,
                                       uint32_t &x0, uint32_t &x1) {
  uint32_t k2 = k0 ^ k1 ^ 0x1BD11BDAu;
  x0 += k0; x1 += k1;
#define TFR(x, r) x = ((x) << (r)) | ((x) >> (32 - (r)))
#define TFS(r) { x0 += x1; TFR(x1, r); x1 ^= x0; }
  TFS(13) TFS(15) TFS(26) TFS(6)
  x0 += k1; x1 += k2 + 1u;
  TFS(17) TFS(29) TFS(16) TFS(24)
  x0 += k2; x1 += k0 + 2u;
  TFS(13) TFS(15) TFS(26) TFS(6)
  x0 += k0; x1 += k1 + 3u;
  TFS(17) TFS(29) TFS(16) TFS(24)
  x0 += k1; x1 += k2 + 4u;
  TFS(13) TFS(15) TFS(26) TFS(6)
  x0 += k2; x1 += k0 + 5u;
#undef TFS
#undef TFR
}

__device__ __forceinline__ float max9(const float* a, int base) {
  float q0 = fmaxf(fmaxf(a[base],         a[base + 1]),         a[base + 2]);
  float q1 = fmaxf(fmaxf(a[base + H2W],   a[base + H2W + 1]),   a[base + H2W + 2]);
  float q2 = fmaxf(fmaxf(a[base + 2*H2W], a[base + 2*H2W + 1]), a[base + 2*H2W + 2]);
  return fmaxf(q0, fmaxf(q1, q2));
}

// ring1 mapping (halo1 border, 100 cells) — pure function of tid
__device__ __forceinline__ void ring1_map(int tid, int &ly, int &lx) {
  if (tid < 34)      { ly = 0;            lx = tid; }
  else if (tid < 68) { ly = 17;           lx = tid - 34; }
  else if (tid < 84) { ly = tid - 68 + 1; lx = 0; }
  else               { ly = tid - 84 + 1; lx = 33; }
}
// ring2 mapping (halo2 border, 108 cells)
__device__ __forceinline__ void ring2_map(int tid, int &ay, int &ax) {
  if (tid < 36)      { ay = 0;            ax = tid; }
  else if (tid < 72) { ay = 19;           ax = tid - 36; }
  else if (tid < 90) { ay = tid - 72 + 1; ax = 0; }
  else               { ay = tid - 90 + 1; ax = 35; }
}

// ---------------- Single persistent fused NCA kernel ----------------
__global__ void __launch_bounds__(256)
nca_persist(const float* __restrict__ xext,
            const float* __restrict__ W1,
            const float* __restrict__ b1,
            const float* __restrict__ W2,
            const float* __restrict__ wvec,
            float* __restrict__ dout) {
  extern __shared__ __align__(16) unsigned char dyn[];
  float* sWz    = (float*)(dyn + SM_WZ);
  ull* sW2p     = (ull*)(dyn + SM_W2);
  ull* sbias    = (ull*)(dyn + SM_BI);
  uint32_t* sbits = (uint32_t*)(dyn + SM_BT);
  float* smx    = (float*)(dyn + SM_MX);
  float* salive = (float*)(dyn + SM_AL);
  float* salpha2 = (float*)(dyn + SM_A2);
  unsigned char* sPL = (unsigned char*)(dyn + SM_PL);
  uint32_t* skey = (uint32_t*)(dyn + SM_KY);
  ulonglong2* szz = (ulonglong2*)(dyn + SM_ZZ);

  int tid = threadIdx.x;
  int blk = blockIdx.x;
  int b = blk / 18;
  int t = blk - b * 18;
  int tcx = t % 3, tcy = t / 3;
  int tx0 = tcx * TIW, ty0 = tcy * TIH;

  // ---- single neighbor per thread (tid 0..7) + flag base ----
  int my_nnb = -1;
  if (tid < 8) {
    int dxy = tid < 4 ? tid : tid + 1;          // skip center
    int dy = dxy / 3 - 1, dx = dxy % 3 - 1;
    int ncx = tcx + dx, ncy = tcy + dy;
    if (ncx >= 0 && ncx < 3 && ncy >= 0 && ncy < 6)
      my_nnb = (b * 18 + ncy * 3 + ncx) * 32;
  }
  int myflag = blk * 32;
  unsigned F0 = *(volatile unsigned*)&g_flagpad[myflag];

  // ---- init: fold weights into smem (threads 0..127) ----
  if (tid < 128) {
    int n = tid;
    const float* w1row = W1 + n * W1COLS;
    #pragma unroll
    for (int k = 0; k < 16; k++) sWz[k * HID + n] = __ldg(w1row + k);
    #pragma unroll
    for (int c = 0; c < 16; c++)
      sWz[(16 + c) * HID + n] = __ldg(w1row + 16 + 2 * c) + __ldg(w1row + 17 + 2 * c);
    #pragma unroll
    for (int c = 0; c < 16; c++) {
      float v = __ldg(W2 + c * HID + n);
      float v1 = __shfl_down_sync(0xffffffffu, v, 1);
      if (!(n & 1)) sW2p[(n >> 1) * 16 + c] = pack2(v, v1);
    }
    const float* wb = wvec + b * 128;
    float a0 = __ldg(b1 + n), a1 = 0.f, a2 = 0.f, a3 = 0.f;
    #pragma unroll
    for (int k = 0; k < 128; k += 4) {
      a0 = fmaf(__ldg(w1row + 48 + k),     __ldg(wb + k),     a0);
      a1 = fmaf(__ldg(w1row + 48 + k + 1), __ldg(wb + k + 1), a1);
      a2 = fmaf(__ldg(w1row + 48 + k + 2), __ldg(wb + k + 2), a2);
      a3 = fmaf(__ldg(w1row + 48 + k + 3), __ldg(wb + k + 3), a3);
    }
    float acc = (a0 + a1) + (a2 + a3);
    float accn = __shfl_down_sync(0xffffffffu, acc, 1);
    if (!(n & 1)) sbias[n >> 1] = pack2(acc, accn);
  }
  if (tid < 64) {
    uint32_t r0 = 0u, r1 = (uint32_t)tid;
    tf2x32(0u, 42u, r0, r1);
    skey[2 * tid] = r0; skey[2 * tid + 1] = r1;
  }
  __syncthreads();

  // ---- init: update bits for all 64 steps x 512 px of this tile ----
  for (int e = tid; e < 512 * NSTEPS; e += 256) {
    int s = e >> 9;
    int p = e & 511;
    int j = b * HW + (ty0 + (p >> 5)) * WW + tx0 + (p & 31);
    uint32_t r0 = 0u, r1 = (uint32_t)j;
    tf2x32(skey[2 * s], skey[2 * s + 1], r0, r1);
    uint32_t word = __ballot_sync(0xffffffffu, ((r0 ^ r1) >> 31) == 0u);
    if ((tid & 31) == 0) sbits[s * 16 + (p >> 5)] = word;
  }

  // ---- init: s=0 tile load (raw x, salive) ----
  {
    const float* xb = xext + b * CHW;
    #pragma unroll
    for (int i = 0; i < 3; i++) {
      int r = tid + i * 256;
      if (r < TSZ) {
        int ly = r / HLW, lx = r - (r / HLW) * HLW;
        int gyy = ty0 + ly - 1, gxx = tx0 + lx - 1;
        bool in = (unsigned)gyy < 96u && (unsigned)gxx < 96u;
        int ofs = gyy * WW + gxx;
        #pragma unroll
        for (int c = 0; c < 16; c++) {
          float v = in ? __ldg(xb + c * HW + ofs) : 0.f;
          smx[c * TSZ + r] = v;
          if (c == 3) salive[r] = in ? v : -1e30f;
        }
      }
    }
  }

  // ---- pixel mapping: 2 x-adjacent px/thread ----
  int pyy = tid >> 4;
  int pxs = (tid & 15) * 2;
  int ctr = (pyy + 1) * HLW + pxs + 1;
  int gy = ty0 + pyy, gx = tx0 + pxs;
  int j0 = b * HW + gy * WW + gx;
  int p0 = pyy * 32 + pxs;
  // boundary band (width 2): only these pixels are ever read by neighbors
  bool store_g = (pyy < 2) | (pyy >= 14) | (pxs == 0) | (pxs == 30);

  __syncthreads();

  for (int s = 0; s < NSTEPS; s++) {
    if (s > 0) {
      const float* __restrict__ Rin = g_R[(s + 1) & 1] + b * CHW;
      const unsigned char* __restrict__ PLin = g_PL[(s + 1) & 1] + b * HW;

      // wait for <=8 neighbors to finish step s-1
      if (my_nnb >= 0) {
        while (*(volatile unsigned*)&g_flagpad[my_nnb] < F0 + (unsigned)s) { }
        __threadfence();
      }
      __syncthreads();

      // ---- phase A: halo-only loads, straight into smem ----
      unsigned char rpl = 0;
      if (tid < 100) {
        int ly, lx;
        ring1_map(tid, ly, lx);
        int gyy = ty0 + ly - 1, gxx = tx0 + lx - 1;
        bool in = (unsigned)gyy < 96u && (unsigned)gxx < 96u;
        int gofs = gyy * WW + gxx;
        int smxr = ly * HLW + lx;
        #pragma unroll
        for (int c = 0; c < 16; c++)
          smx[c * TSZ + smxr] = in ? __ldcg(Rin + c * HW + gofs) : 0.f;
        rpl = in ? __ldcg(PLin + gofs) : 0;
        salpha2[(ly + 1) * H2W + lx + 1] = in ? smx[3 * TSZ + smxr] : -1e30f;
      }
      if (tid < 108) {
        int ay, ax;
        ring2_map(tid, ay, ax);
        int gyy = ty0 + ay - 2, gxx = tx0 + ax - 2;
        bool in = (unsigned)gyy < 96u && (unsigned)gxx < 96u;
        salpha2[ay * H2W + ax] = in ? __ldcg(Rin + 3 * HW + gyy * WW + gxx) : -1e30f;
      }
      // interior alpha from smem
      {
        int iy0 = tid >> 5, ix0 = tid & 31;
        salpha2[(iy0 + 2) * H2W + ix0 + 2]  = smx[3 * TSZ + (iy0 + 1) * HLW + ix0 + 1];
        salpha2[(iy0 + 10) * H2W + ix0 + 2] = smx[3 * TSZ + (iy0 + 9) * HLW + ix0 + 1];
      }
      __syncthreads();

      // ---- phase B: life masks; zero only dead cells in place ----
      {
        int iy0 = tid >> 5, ix0 = tid & 31;
        int c0_a2 = (iy0 + 2) * H2W + ix0 + 2;
        int c0_src = (iy0 + 1) * HLW + ix0 + 1;
        float m = max9(salpha2, c0_a2 - H2W - 1);
        bool f = sPL[tid] && m > 0.1f;
        salive[c0_src] = f ? salpha2[c0_a2] : 0.f;
        if (!f) {
          #pragma unroll
          for (int c = 0; c < 16; c++) smx[c * TSZ + c0_src] = 0.f;
        }
        int c1_a2 = (iy0 + 10) * H2W + ix0 + 2;
        int c1_src = (iy0 + 9) * HLW + ix0 + 1;
        float m2 = max9(salpha2, c1_a2 - H2W - 1);
        bool f2 = sPL[tid + 256] && m2 > 0.1f;
        salive[c1_src] = f2 ? salpha2[c1_a2] : 0.f;
        if (!f2) {
          #pragma unroll
          for (int c = 0; c < 16; c++) smx[c * TSZ + c1_src] = 0.f;
        }
      }
      if (tid < 100) {
        int ly, lx;
        ring1_map(tid, ly, lx);
        int gyy = ty0 + ly - 1, gxx = tx0 + lx - 1;
        bool in = (unsigned)gyy < 96u && (unsigned)gxx < 96u;
        int smxr = ly * HLW + lx;
        float m = max9(salpha2, ly * H2W + lx);
        bool f = in && rpl && m > 0.1f;
        salive[smxr] = in ? (f ? salpha2[(ly + 1) * H2W + lx + 1] : 0.f) : -1e30f;
        if (!f) {
          #pragma unroll
          for (int c = 0; c < 16; c++) smx[c * TSZ + smxr] = 0.f;
        }
      }
      __syncthreads();
    }

    // ---- stencil: raw + sobel for both pixels; z stored packed to smem ----
    float za3 = 0.f, zb3 = 0.f;
    #pragma unroll
    for (int c = 0; c < 16; c++) {
      const float* a = smx + c * TSZ;
      float tu0 = a[ctr - HLW - 1], tu1 = a[ctr - HLW], tu2 = a[ctr - HLW + 1], tu3 = a[ctr - HLW + 2];
      float tc0 = a[ctr - 1],       tc1 = a[ctr],       tc2 = a[ctr + 1],       tc3 = a[ctr + 2];
      float td0 = a[ctr + HLW - 1], td1 = a[ctr + HLW], td2 = a[ctr + HLW + 1], td3 = a[ctr + HLW + 2];
      float sa, sb;
      if (c < 8) {
        sa = (tu2 - tu0) + 2.f * (tc2 - tc0) + (td2 - td0);
        sb = (tu3 - tu1) + 2.f * (tc3 - tc1) + (td3 - td1);
      } else {
        sa = (td0 - tu0) + 2.f * (td1 - tu1) + (td2 - tu2);
        sb = (td1 - tu1) + 2.f * (td2 - tu2) + (td3 - tu3);
      }
      ulonglong2 zr, zs;
      zr.x = pack2(tc1, tc1); zr.y = pack2(tc2, tc2);
      zs.x = pack2(sa, sa);   zs.y = pack2(sb, sb);
      szz[c * 256 + tid] = zr;
      szz[(16 + c) * 256 + tid] = zs;
      if (c == 3) { za3 = tc1; zb3 = tc2; }
    }

    // pre_life: 3x3 max over masked alpha (-inf OOB)
    float m0, m1;
    {
      const float* al = salive;
      float au0 = al[ctr - HLW - 1], au1 = al[ctr - HLW], au2 = al[ctr - HLW + 1], au3 = al[ctr - HLW + 2];
      float ac0 = al[ctr - 1],       ac1 = al[ctr],       ac2 = al[ctr + 1],       ac3 = al[ctr + 2];
      float ad0 = al[ctr + HLW - 1], ad1 = al[ctr + HLW], ad2 = al[ctr + HLW + 1], ad3 = al[ctr + HLW + 2];
      float mid = fmaxf(fmaxf(au1, au2), fmaxf(fmaxf(ac1, ac2), fmaxf(ad1, ad2)));
      m0 = fmaxf(mid, fmaxf(au0, fmaxf(ac0, ad0)));
      m1 = fmaxf(mid, fmaxf(au3, fmaxf(ac3, ad3)));
    }
    __syncthreads();   // all smx/salive stencil reads done before end-of-step overwrite

    // ---- MLP: 4 quarters of 32 hidden units; z from szz (no per-iter packing) ----
    ull acc2a[16], acc2b[16];
    #pragma unroll
    for (int i = 0; i < 16; i++) { acc2a[i] = 0ull; acc2b[i] = 0ull; }

    #pragma unroll 1
    for (int q = 0; q < 4; q++) {
      ull ha[16], hb[16];
      {
        const ulonglong2* bbp = (const ulonglong2*)(sbias + q * 16);
        #pragma unroll
        for (int i = 0; i < 8; i++) {
          ulonglong2 v = bbp[i];
          ha[2 * i] = v.x; ha[2 * i + 1] = v.y;
          hb[2 * i] = v.x; hb[2 * i + 1] = v.y;
        }
      }
      #pragma unroll 8
      for (int k = 0; k < 32; k++) {
        ulonglong2 zz = szz[k * 256 + tid];
        const ulonglong2* wv = (const ulonglong2*)(sWz + k * HID + q * 32);
        #pragma unroll
        for (int i = 0; i < 8; i++) {
          ulonglong2 v = wv[i];
          ha[2 * i]     = fma2(zz.x, v.x, ha[2 * i]);
          ha[2 * i + 1] = fma2(zz.x, v.y, ha[2 * i + 1]);
          hb[2 * i]     = fma2(zz.y, v.x, hb[2 * i]);
          hb[2 * i + 1] = fma2(zz.y, v.y, hb[2 * i + 1]);
        }
      }
      #pragma unroll 4
      for (int pp = 0; pp < 16; pp++) {
        float2 fa = unpack2(ha[pp]);
        float2 fb = unpack2(hb[pp]);
        ull hra = pack2(fmaxf(fa.x, 0.f), fmaxf(fa.y, 0.f));
        ull hrb = pack2(fmaxf(fb.x, 0.f), fmaxf(fb.y, 0.f));
        const ulonglong2* w2 = (const ulonglong2*)(sW2p + (q * 16 + pp) * 16);
        #pragma unroll
        for (int qq = 0; qq < 8; qq++) {
          ulonglong2 v = w2[qq];
          acc2a[2 * qq]     = fma2(hra, v.x, acc2a[2 * qq]);
          acc2a[2 * qq + 1] = fma2(hra, v.y, acc2a[2 * qq + 1]);
          acc2b[2 * qq]     = fma2(hrb, v.x, acc2b[2 * qq]);
          acc2b[2 * qq + 1] = fma2(hrb, v.y, acc2b[2 * qq + 1]);
        }
      }
    }

    // ---- stochastic gate + state write (smem always; global only boundary band) ----
    uint32_t wbits = sbits[s * 16 + pyy];
    float u0 = (((wbits >> pxs) & 1u) && za3 > 0.1f) ? 1.f : 0.f;
    float u1 = (((wbits >> (pxs + 1)) & 1u) && zb3 > 0.1f) ? 1.f : 0.f;

    float* Rout = g_R[s & 1] + b * CHW + gy * WW + gx;
    #pragma unroll
    for (int c = 0; c < 16; c++) {
      ulonglong2 zr = szz[c * 256 + tid];
      float raw_a = unpack2(zr.x).x;
      float raw_b = unpack2(zr.y).x;
      float2 da = unpack2(acc2a[c]);
      float2 db = unpack2(acc2b[c]);
      float2 o;
      o.x = fmaf(da.x + da.y, u0, raw_a);
      o.y = fmaf(db.x + db.y, u1, raw_b);
      if (store_g) __stcg((float2*)(Rout + c * HW), o);
      smx[c * TSZ + ctr] = o.x;
      smx[c * TSZ + ctr + 1] = o.y;
    }
    {
      unsigned char l0 = m0 > 0.1f ? 1 : 0;
      unsigned char l1 = m1 > 0.1f ? 1 : 0;
      if (store_g) {
        unsigned short pl = (unsigned short)(l0 | ((unsigned)l1 << 8));
        __stcg((unsigned short*)(g_PL[s & 1] + j0), pl);
      }
      sPL[p0] = l0;
      sPL[p0 + 1] = l1;
    }

    __syncthreads();
    if (tid == 0) {
      __threadfence();
      *(volatile unsigned*)&g_flagpad[myflag] = F0 + (unsigned)(s + 1);
    }
  }

  // ---- final alive masking -> d_out (interior from smem; ring1 alpha from global) ----
  {
    const float* __restrict__ Rin = g_R[(NSTEPS - 1) & 1] + b * CHW;
    if (my_nnb >= 0) {
      while (*(volatile unsigned*)&g_flagpad[my_nnb] < F0 + (unsigned)NSTEPS) { }
      __threadfence();
    }
    __syncthreads();
    if (tid < 100) {
      int ly, lx;
      ring1_map(tid, ly, lx);
      int gyy = ty0 + ly - 1, gxx = tx0 + lx - 1;
      bool in = (unsigned)gyy < 96u && (unsigned)gxx < 96u;
      salpha2[(ly + 1) * H2W + lx + 1] = in ? __ldcg(Rin + 3 * HW + gyy * WW + gxx) : -1e30f;
    }
    {
      int iy0 = tid >> 5, ix0 = tid & 31;
      salpha2[(iy0 + 2) * H2W + ix0 + 2]  = smx[3 * TSZ + (iy0 + 1) * HLW + ix0 + 1];
      salpha2[(iy0 + 10) * H2W + ix0 + 2] = smx[3 * TSZ + (iy0 + 9) * HLW + ix0 + 1];
    }
    __syncthreads();

    int w0 = (pyy + 1) * H2W + pxs + 1;
    float mm0 = max9(salpha2, w0);
    float mm1 = max9(salpha2, w0 + 1);
    float sc0 = (sPL[p0] && mm0 > 0.1f) ? 1.f : 0.f;
    float sc1 = (sPL[p0 + 1] && mm1 > 0.1f) ? 1.f : 0.f;

    float* ob = dout + b * CHW + gy * WW + gx;
    #pragma unroll
    for (int c = 0; c < 16; c++) {
      float2 v;
      v.x = smx[c * TSZ + ctr] * sc0;
      v.y = smx[c * TSZ + ctr + 1] * sc1;
      *(float2*)(ob + c * HW) = v;
    }
  }
}

// ---------------- Host ----------------
extern "C" void kernel_launch(void* const* d_in, const int* in_sizes, int n_in,
                              void* d_out, int out_size) {
  (void)in_sizes; (void)n_in; (void)out_size;
  const float* x  = (const float*)d_in[0];
  const float* w  = (const float*)d_in[1];
  const float* W1 = (const float*)d_in[3];
  const float* b1 = (const float*)d_in[4];
  const float* W2 = (const float*)d_in[5];

  cudaFuncSetAttribute(nca_persist, cudaFuncAttributeMaxDynamicSharedMemorySize, SM_TOT);
  nca_persist<<<NBLK, 256, SM_TOT>>>(x, W1, b1, W2, w, (float*)d_out);
}

// round 16
// speedup vs baseline: 1.5965x; 1.5965x over previous
#include <cuda_runtime.h>
#include <stdint.h>

#define NB 8
#define HH 96
#define WW 96
#define HW 9216
#define CHW 147456
#define NPIX 73728
#define HID 128
#define NSTEPS 64
#define W1COLS 176

#define TIW 32
#define TIH 16
#define HLW 34
#define HLH 18
#define TSZ 612          // HLW*HLH (halo1)
#define H2W 36
#define H2H 20
#define H2SZ 720         // halo2
#define NBLK 144         // 8 batches * (3x6 tiles)

// dynamic smem layout (bytes)
#define SM_WZ 0          // float[32*128]   16384
#define SM_W2 16384      // ull[64*16]       8192
#define SM_BI 24576      // ull[64]           512
#define SM_MX 25088      // float[16*612]   39168
#define SM_AL 64256      // float[612]       2448
#define SM_A2 66704      // float[720]       2880
#define SM_SZ 69584      // float2[32*256]  65536  (per-thread z pairs)
#define SM_TOT 135120

typedef unsigned long long ull;

// Scratch (allocation-free)
__device__ float g_R[2][NB * CHW];
__device__ unsigned char g_PL[2][NPIX];
__device__ uint32_t g_updbits[NSTEPS * (NPIX / 32)];
__device__ float g_Wz[32 * HID];
__device__ ull g_W2p[64 * 16];
__device__ ull g_biasP[NB * 64];
__device__ unsigned g_flagpad[NBLK * 32];   // per-block step flag, 128B stride

// ---------------- f32x2 helpers ----------------
__device__ __forceinline__ ull fma2(ull a, ull b, ull c) {
  ull d;
  asm("fma.rn.f32x2 %0, %1, %2, %3;" : "=l"(d) : "l"(a), "l"(b), "l"(c));
  return d;
}
__device__ __forceinline__ ull pack2(float lo, float hi) {
  ull r;
  asm("mov.b64 %0, {%1, %2};" : "=l"(r) : "f"(lo), "f"(hi));
  return r;
}
__device__ __forceinline__ float2 unpack2(ull v) {
  float2 f;
  asm("mov.b64 {%0, %1}, %2;" : "=f"(f.x), "=f"(f.y) : "l"(v));
  return f;
}

// ---------------- Threefry-2x32 (matches JAX partitionable) ----------------
__device__ __forceinline__ void tf2x32(uint32_t k0, uint32_t k1,
                                       uint32_t &x0, uint32_t &x1) {
  uint32_t k2 = k0 ^ k1 ^ 0x1BD11BDAu;
  x0 += k0; x1 += k1;
#define TFR(x, r) x = ((x) << (r)) | ((x) >> (32 - (r)))
#define TFS(r) { x0 += x1; TFR(x1, r); x1 ^= x0; }
  TFS(13) TFS(15) TFS(26) TFS(6)
  x0 += k1; x1 += k2 + 1u;
  TFS(17) TFS(29) TFS(16) TFS(24)
  x0 += k2; x1 += k0 + 2u;
  TFS(13) TFS(15) TFS(26) TFS(6)
  x0 += k0; x1 += k1 + 3u;
  TFS(17) TFS(29) TFS(16) TFS(24)
  x0 += k1; x1 += k2 + 4u;
  TFS(13) TFS(15) TFS(26) TFS(6)
  x0 += k2; x1 += k0 + 5u;
#undef TFS
#undef TFR
}

// ---------------- Precompute (parallel over batches) + flag reset ----------------
__global__ void precompute_kernel(const float* __restrict__ W1,
                                  const float* __restrict__ b1,
                                  const float* __restrict__ W2,
                                  const float* __restrict__ w) {
  int n = threadIdx.x;
  int b = blockIdx.x;
  // reset neighbor-sync flags every launch (graph-replay determinism)
  for (int i = b * 128 + n; i < NBLK * 32; i += NB * 128) g_flagpad[i] = 0u;
  if (n >= HID) return;
  const float* w1row = W1 + n * W1COLS;

  if (b == 0) {
    #pragma unroll
    for (int k = 0; k < 16; k++) g_Wz[k * HID + n] = w1row[k];
    #pragma unroll
    for (int c = 0; c < 16; c++)
      g_Wz[(16 + c) * HID + n] = w1row[16 + 2 * c] + w1row[17 + 2 * c];
    if (!(n & 1)) {
      int p = n >> 1;
      #pragma unroll
      for (int c = 0; c < 16; c++)
        g_W2p[p * 16 + c] = pack2(W2[c * HID + n], W2[c * HID + n + 1]);
    }
  }

  const float* wb = w + b * 128;
  float a0 = b1[n], a1 = 0.f, a2 = 0.f, a3 = 0.f;
  #pragma unroll
  for (int k = 0; k < 128; k += 4) {
    a0 = fmaf(w1row[48 + k],     __ldg(wb + k),     a0);
    a1 = fmaf(w1row[48 + k + 1], __ldg(wb + k + 1), a1);
    a2 = fmaf(w1row[48 + k + 2], __ldg(wb + k + 2), a2);
    a3 = fmaf(w1row[48 + k + 3], __ldg(wb + k + 3), a3);
  }
  float acc = (a0 + a1) + (a2 + a3);
  float accn1 = __shfl_down_sync(0xffffffffu, acc, 1);
  if (!(n & 1)) g_biasP[b * 64 + (n >> 1)] = pack2(acc, accn1);
}

// ---------------- Precompute threefry update bits for all steps ----------------
__global__ void maskgen_kernel() {
  int s = blockIdx.y;
  int j = blockIdx.x * 256 + threadIdx.x;
  uint32_t k0 = 0u, k1 = (uint32_t)s;
  tf2x32(0u, 42u, k0, k1);
  uint32_t r0 = 0u, r1 = (uint32_t)j;
  tf2x32(k0, k1, r0, r1);
  uint32_t bits = r0 ^ r1;
  uint32_t word = __ballot_sync(0xffffffffu, bits < 0x80000000u);
  if ((threadIdx.x & 31) == 0) g_updbits[s * (NPIX / 32) + (j >> 5)] = word;
}

// ---------------- Persistent fused NCA kernel (neighbor-flag sync) ----------------
__global__ void __launch_bounds__(256)
nca_persist(const float* __restrict__ xext, float* __restrict__ dout) {
  extern __shared__ __align__(16) unsigned char dyn[];
  float* sWz = (float*)(dyn + SM_WZ);
  ull* sW2p  = (ull*)(dyn + SM_W2);
  ull* sbias = (ull*)(dyn + SM_BI);
  float* smx = (float*)(dyn + SM_MX);
  float* salive = (float*)(dyn + SM_AL);
  float* salpha2 = (float*)(dyn + SM_A2);
  float2* szf2 = (float2*)(dyn + SM_SZ);

  int tid = threadIdx.x;
  int blk = blockIdx.x;
  int b = blk / 18;
  int t = blk - b * 18;
  int tcx = t % 3, tcy = t / 3;
  int tx0 = tcx * TIW;
  int ty0 = tcy * TIH;

  // ---- neighbor list (batch-local, <=8) ----
  int nnb[8];
  int nn = 0;
  #pragma unroll
  for (int dy = -1; dy <= 1; dy++)
    #pragma unroll
    for (int dx = -1; dx <= 1; dx++) {
      if (dx == 0 && dy == 0) continue;
      int ncx = tcx + dx, ncy = tcy + dy;
      if (ncx >= 0 && ncx < 3 && ncy >= 0 && ncy < 6)
        nnb[nn++] = (b * 18 + ncy * 3 + ncx) * 32;
    }
  int myflag = blk * 32;

  // ---- load weights once ----
  {
    const float4* g1 = (const float4*)g_Wz;
    float4* s1 = (float4*)sWz;
    #pragma unroll
    for (int i = tid; i < 32 * HID / 4; i += 256) s1[i] = g1[i];
    const float4* g2 = (const float4*)g_W2p;
    float4* s2 = (float4*)sW2p;
    #pragma unroll
    for (int i = tid; i < 512; i += 256) s2[i] = g2[i];
    if (tid < 64) sbias[tid] = g_biasP[b * 64 + tid];
  }

  // ---- slots: halo1 (612 cells, w=34): 3/thread; halo2 (720 cells, w=36): 3/thread ----
  int fofs[3], sly[3], slx[3];
  bool fin[3], fvalid[3];
  #pragma unroll
  for (int i = 0; i < 3; i++) {
    int r = tid + i * 256;
    int ly = r / HLW, lx = r - (r / HLW) * HLW;
    int gy = ty0 + ly - 1, gx = tx0 + lx - 1;
    sly[i] = ly; slx[i] = lx;
    fvalid[i] = r < TSZ;
    fin[i] = fvalid[i] && ((unsigned)gy < 96u) && ((unsigned)gx < 96u);
    fofs[i] = gy * WW + gx;
  }
  int aofs[3];
  bool ain[3], avalid[3];
  #pragma unroll
  for (int i = 0; i < 3; i++) {
    int r = tid + i * 256;
    int ay = r / H2W, ax = r - (r / H2W) * H2W;
    int gy = ty0 + ay - 2, gx = tx0 + ax - 2;
    avalid[i] = r < H2SZ;
    ain[i] = avalid[i] && ((unsigned)gy < 96u) && ((unsigned)gx < 96u);
    aofs[i] = gy * WW + gx;
  }

  // ---- pixel mapping: 2 x-adjacent px/thread ----
  int pyy = tid >> 4;
  int pxs = (tid & 15) * 2;
  int ctr = (pyy + 1) * HLW + pxs + 1;
  int gy = ty0 + pyy, gx = tx0 + pxs;
  int j0 = b * HW + gy * WW + gx;
  int sh = j0 & 31;

  for (int s = 0; s < NSTEPS; s++) {
    const float* __restrict__ Rin = g_R[(s + 1) & 1] + b * CHW;
    const unsigned char* __restrict__ PLin = g_PL[(s + 1) & 1] + b * HW;

    if (s == 0) {
      const float* xb = xext + b * CHW;
      #pragma unroll 1
      for (int c = 0; c < 16; c++) {
        const float* src = xb + c * HW;
        #pragma unroll
        for (int i = 0; i < 3; i++) {
          int r = tid + i * 256;
          if (fvalid[i]) {
            float v = fin[i] ? __ldg(src + fofs[i]) : 0.f;
            smx[c * TSZ + r] = v;
            if (c == 3) salive[r] = fin[i] ? v : -1e30f;
          }
        }
      }
    } else {
      // ---- wait for <=8 neighbors to finish step s-1 ----
      if (tid < nn) {
        while (*(volatile unsigned*)&g_flagpad[nnb[tid]] < (unsigned)s) { }
        __threadfence();
      }
      __syncthreads();
      // ---- phase A: ONE batched round trip (alpha2 + PL + 15 channels) ----
      #pragma unroll
      for (int i = 0; i < 3; i++) {
        int r = tid + i * 256;
        if (avalid[i])
          salpha2[r] = ain[i] ? __ldcg(Rin + 3 * HW + aofs[i]) : -1e30f;
      }
      unsigned char plr[3];
      #pragma unroll
      for (int i = 0; i < 3; i++)
        plr[i] = fin[i] ? __ldcg(PLin + fofs[i]) : 0;
      float st[3][16];
      #pragma unroll
      for (int i = 0; i < 3; i++) {
        if (fvalid[i]) {
          #pragma unroll
          for (int c = 0; c < 16; c++)
            if (c != 3) st[i][c] = fin[i] ? __ldcg(Rin + c * HW + fofs[i]) : 0.f;
        }
      }
      __syncthreads();
      // ---- phase B: life mask locally, write masked tile ----
      #pragma unroll
      for (int i = 0; i < 3; i++) {
        int r = tid + i * 256;
        if (fvalid[i]) {
          float m = -1e30f;
          #pragma unroll
          for (int dy = 0; dy < 3; dy++) {
            const float* row = salpha2 + (sly[i] + dy) * H2W + slx[i];
            m = fmaxf(m, fmaxf(fmaxf(row[0], row[1]), row[2]));
          }
          float a3raw = salpha2[(sly[i] + 1) * H2W + slx[i] + 1];
          float sc = (fin[i] && m > 0.1f && plr[i]) ? 1.f : 0.f;
          #pragma unroll
          for (int c = 0; c < 16; c++)
            smx[c * TSZ + r] = (c == 3 ? a3raw : st[i][c]) * sc;
          salive[r] = fin[i] ? a3raw * sc : -1e30f;
        }
      }
    }
    __syncthreads();

    // ---- stencil: raw + sobel for both pixels; z -> float2 smem buffer ----
    float za3, zb3;
    #pragma unroll
    for (int c = 0; c < 16; c++) {
      const float* a = smx + c * TSZ;
      float tu0 = a[ctr - HLW - 1], tu1 = a[ctr - HLW], tu2 = a[ctr - HLW + 1], tu3 = a[ctr - HLW + 2];
      float tc0 = a[ctr - 1],       tc1 = a[ctr],       tc2 = a[ctr + 1],       tc3 = a[ctr + 2];
      float td0 = a[ctr + HLW - 1], td1 = a[ctr + HLW], td2 = a[ctr + HLW + 1], td3 = a[ctr + HLW + 2];
      float sa, sb;
      if (c < 8) {
        sa = (tu2 - tu0) + 2.f * (tc2 - tc0) + (td2 - td0);
        sb = (tu3 - tu1) + 2.f * (tc3 - tc1) + (td3 - td1);
      } else {
        sa = (td0 - tu0) + 2.f * (td1 - tu1) + (td2 - tu2);
        sb = (td1 - tu1) + 2.f * (td2 - tu2) + (td3 - tu3);
      }
      float2 zr; zr.x = tc1; zr.y = tc2;
      float2 zs; zs.x = sa;  zs.y = sb;
      szf2[c * 256 + tid] = zr;
      szf2[(16 + c) * 256 + tid] = zs;
      if (c == 3) { za3 = tc1; zb3 = tc2; }
    }

    // pre_life: 3x3 max over masked alpha (-inf OOB)
    float m0, m1;
    {
      const float* al = salive;
      float au0 = al[ctr - HLW - 1], au1 = al[ctr - HLW], au2 = al[ctr - HLW + 1], au3 = al[ctr - HLW + 2];
      float ac0 = al[ctr - 1],       ac1 = al[ctr],       ac2 = al[ctr + 1],       ac3 = al[ctr + 2];
      float ad0 = al[ctr + HLW - 1], ad1 = al[ctr + HLW], ad2 = al[ctr + HLW + 1], ad3 = al[ctr + HLW + 2];
      float mid = fmaxf(fmaxf(au1, au2), fmaxf(fmaxf(ac1, ac2), fmaxf(ad1, ad2)));
      m0 = fmaxf(mid, fmaxf(au0, fmaxf(ac0, ad0)));
      m1 = fmaxf(mid, fmaxf(au3, fmaxf(ac3, ad3)));
    }

    // ---- MLP: hidden-pair f32x2; z from float2 smem (frees za/zb registers) ----
    ull acc2a[16], acc2b[16];
    #pragma unroll
    for (int i = 0; i < 16; i++) { acc2a[i] = 0ull; acc2b[i] = 0ull; }

    #pragma unroll 1
    for (int gc = 0; gc < 8; gc++) {
      ull ha[8], hb[8];
      {
        const ulonglong2* bb = (const ulonglong2*)(sbias + gc * 8);
        #pragma unroll
        for (int i = 0; i < 4; i++) {
          ulonglong2 v = bb[i];
          ha[2 * i] = v.x; ha[2 * i + 1] = v.y;
          hb[2 * i] = v.x; hb[2 * i + 1] = v.y;
        }
      }
      #pragma unroll
      for (int k = 0; k < 32; k++) {
        float2 zv = szf2[k * 256 + tid];
        ull wza = pack2(zv.x, zv.x);
        ull wzb = pack2(zv.y, zv.y);
        const ulonglong2* wv = (const ulonglong2*)(sWz + k * HID + gc * 16);
        #pragma unroll
        for (int i = 0; i < 4; i++) {
          ulonglong2 v = wv[i];
          ha[2 * i]     = fma2(wza, v.x, ha[2 * i]);
          ha[2 * i + 1] = fma2(wza, v.y, ha[2 * i + 1]);
          hb[2 * i]     = fma2(wzb, v.x, hb[2 * i]);
          hb[2 * i + 1] = fma2(wzb, v.y, hb[2 * i + 1]);
        }
      }
      #pragma unroll
      for (int pp = 0; pp < 8; pp++) {
        float2 fa = unpack2(ha[pp]);
        float2 fb = unpack2(hb[pp]);
        ull hra = pack2(fmaxf(fa.x, 0.f), fmaxf(fa.y, 0.f));
        ull hrb = pack2(fmaxf(fb.x, 0.f), fmaxf(fb.y, 0.f));
        const ulonglong2* w2 = (const ulonglong2*)(sW2p + (gc * 8 + pp) * 16);
        #pragma unroll
        for (int q = 0; q < 8; q++) {
          ulonglong2 v = w2[q];
          acc2a[2 * q]     = fma2(hra, v.x, acc2a[2 * q]);
          acc2a[2 * q + 1] = fma2(hra, v.y, acc2a[2 * q + 1]);
          acc2b[2 * q]     = fma2(hrb, v.x, acc2b[2 * q]);
          acc2b[2 * q + 1] = fma2(hrb, v.y, acc2b[2 * q + 1]);
        }
      }
    }

    // ---- stochastic gate + state write ----
    uint32_t wbits = __ldg(g_updbits + s * (NPIX / 32) + (j0 >> 5));
    float u0 = (((wbits >> sh) & 1u) && za3 > 0.1f) ? 1.f : 0.f;
    float u1 = (((wbits >> (sh + 1)) & 1u) && zb3 > 0.1f) ? 1.f : 0.f;

    float* Rout = g_R[s & 1] + b * CHW + gy * WW + gx;
    #pragma unroll
    for (int c = 0; c < 16; c++) {
      float2 zr = szf2[c * 256 + tid];
      float2 da = unpack2(acc2a[c]);
      float2 db = unpack2(acc2b[c]);
      float2 o;
      o.x = fmaf(da.x + da.y, u0, zr.x);
      o.y = fmaf(db.x + db.y, u1, zr.y);
      __stcg((float2*)(Rout + c * HW), o);
    }
    {
      unsigned short pl = (unsigned short)((m0 > 0.1f ? 1u : 0u) | ((m1 > 0.1f ? 1u : 0u) << 8));
      __stcg((unsigned short*)(g_PL[s & 1] + j0), pl);
    }

    __syncthreads();
    if (tid == 0) {
      __threadfence();
      *(volatile unsigned*)&g_flagpad[myflag] = (unsigned)(s + 1);
    }
  }

  // ---- final alive masking -> d_out ----
  {
    const float* __restrict__ Rin = g_R[(NSTEPS - 1) & 1] + b * CHW;
    const unsigned char* __restrict__ PLin = g_PL[(NSTEPS - 1) & 1] + b * HW;
    if (tid < nn) {
      while (*(volatile unsigned*)&g_flagpad[nnb[tid]] < (unsigned)NSTEPS) { }
      __threadfence();
    }
    __syncthreads();
    #pragma unroll
    for (int i = 0; i < 3; i++) {
      int r = tid + i * 256;
      if (avalid[i])
        salpha2[r] = ain[i] ? __ldcg(Rin + 3 * HW + aofs[i]) : -1e30f;
    }
    unsigned char plr[3];
    #pragma unroll
    for (int i = 0; i < 3; i++)
      plr[i] = fin[i] ? __ldcg(PLin + fofs[i]) : 0;
    float st[3][16];
    #pragma unroll
    for (int i = 0; i < 3; i++) {
      if (fvalid[i]) {
        #pragma unroll
        for (int c = 0; c < 16; c++)
          if (c != 3) st[i][c] = fin[i] ? __ldcg(Rin + c * HW + fofs[i]) : 0.f;
      }
    }
    __syncthreads();
    #pragma unroll
    for (int i = 0; i < 3; i++) {
      int r = tid + i * 256;
      if (fvalid[i]) {
        float m = -1e30f;
        #pragma unroll
        for (int dy = 0; dy < 3; dy++) {
          const float* row = salpha2 + (sly[i] + dy) * H2W + slx[i];
          m = fmaxf(m, fmaxf(fmaxf(row[0], row[1]), row[2]));
        }
        float a3raw = salpha2[(sly[i] + 1) * H2W + slx[i] + 1];
        float sc = (fin[i] && m > 0.1f && plr[i]) ? 1.f : 0.f;
        #pragma unroll
        for (int c = 0; c < 16; c++)
          smx[c * TSZ + r] = (c == 3 ? a3raw : st[i][c]) * sc;
      }
    }
    __syncthreads();

    float* ob = dout + b * CHW + gy * WW + gx;
    #pragma unroll
    for (int c = 0; c < 16; c++) {
      float2 v;
      v.x = smx[c * TSZ + ctr];
      v.y = smx[c * TSZ + ctr + 1];
      *(float2*)(ob + c * HW) = v;
    }
  }
}

// ---------------- Host ----------------
extern "C" void kernel_launch(void* const* d_in, const int* in_sizes, int n_in,
                              void* d_out, int out_size) {
  (void)in_sizes; (void)n_in; (void)out_size;
  const float* x  = (const float*)d_in[0];
  const float* w  = (const float*)d_in[1];
  const float* W1 = (const float*)d_in[3];
  const float* b1 = (const float*)d_in[4];
  const float* W2 = (const float*)d_in[5];

  cudaFuncSetAttribute(nca_persist, cudaFuncAttributeMaxDynamicSharedMemorySize, SM_TOT);

  precompute_kernel<<<NB, 128>>>(W1, b1, W2, w);
  maskgen_kernel<<<dim3(NPIX / 256, NSTEPS), 256>>>();
  nca_persist<<<NBLK, 256, SM_TOT>>>(x, (float*)d_out);
}

// round 17
// speedup vs baseline: 1.6768x; 1.0503x over previous
#include <cuda_runtime.h>
#include <stdint.h>

#define NB 8
#define HH 96
#define WW 96
#define HW 9216
#define CHW 147456
#define NPIX 73728
#define HID 128
#define NSTEPS 64
#define W1COLS 176

#define TIW 32
#define TIH 16
#define HLW 34
#define HLH 18
#define TSZ 612          // HLW*HLH (halo1)
#define H2W 36
#define H2H 20
#define H2SZ 720         // halo2
#define NBLK 144         // 8 batches * (3x6 tiles)

// dynamic smem layout (bytes)
#define SM_WZ 0          // float[32*128]   16384
#define SM_W2 16384      // ull[64*16]       8192
#define SM_BI 24576      // ull[64]           512
#define SM_MX 25088      // float[16*612]   39168
#define SM_AL 64256      // float[612]       2448
#define SM_A2 66704      // float[720]       2880
#define SM_TOT 69584

typedef unsigned long long ull;

// Scratch (allocation-free)
__device__ float g_R[2][NB * CHW];
__device__ unsigned char g_PL[2][NPIX];
__device__ uint32_t g_updbits[NSTEPS * (NPIX / 32)];
__device__ float g_Wz[32 * HID];
__device__ ull g_W2p[64 * 16];
__device__ ull g_biasP[NB * 64];
__device__ unsigned g_flagpad[NBLK * 32];   // per-block step flag, 128B stride

// ---------------- f32x2 helpers ----------------
__device__ __forceinline__ ull fma2(ull a, ull b, ull c) {
  ull d;
  asm("fma.rn.f32x2 %0, %1, %2, %3;" : "=l"(d) : "l"(a), "l"(b), "l"(c));
  return d;
}
__device__ __forceinline__ ull pack2(float lo, float hi) {
  ull r;
  asm("mov.b64 %0, {%1, %2};" : "=l"(r) : "f"(lo), "f"(hi));
  return r;
}
__device__ __forceinline__ float2 unpack2(ull v) {
  float2 f;
  asm("mov.b64 {%0, %1}, %2;" : "=f"(f.x), "=f"(f.y) : "l"(v));
  return f;
}

// ---------------- Threefry-2x32 (matches JAX partitionable) ----------------
__device__ __forceinline__ void tf2x32(uint32_t k0, uint32_t k1,
                                       uint32_t &x0, uint32_t &x1) {
  uint32_t k2 = k0 ^ k1 ^ 0x1BD11BDAu;
  x0 += k0; x1 += k1;
#define TFR(x, r) x = ((x) << (r)) | ((x) >> (32 - (r)))
#define TFS(r) { x0 += x1; TFR(x1, r); x1 ^= x0; }
  TFS(13) TFS(15) TFS(26) TFS(6)
  x0 += k1; x1 += k2 + 1u;
  TFS(17) TFS(29) TFS(16) TFS(24)
  x0 += k2; x1 += k0 + 2u;
  TFS(13) TFS(15) TFS(26) TFS(6)
  x0 += k0; x1 += k1 + 3u;
  TFS(17) TFS(29) TFS(16) TFS(24)
  x0 += k1; x1 += k2 + 4u;
  TFS(13) TFS(15) TFS(26) TFS(6)
  x0 += k2; x1 += k0 + 5u;
#undef TFS
#undef TFR
}

// ---------------- ONE merged init kernel: maskgen (y<64) + precompute (y==64) ----------------
// grid: dim3(72, 65), block: 256.
__global__ void init_kernel(const float* __restrict__ W1,
                            const float* __restrict__ b1,
                            const float* __restrict__ W2,
                            const float* __restrict__ w) {
  int tid = threadIdx.x;
  if (blockIdx.y < NSTEPS) {
    // ---- maskgen: 4 pixel-words per block-slice ----
    int s = blockIdx.y;
    uint32_t k0 = 0u, k1 = (uint32_t)s;
    tf2x32(0u, 42u, k0, k1);            // keys[s]
    #pragma unroll
    for (int it = 0; it < 4; it++) {
      int j = blockIdx.x * 1024 + it * 256 + tid;
      uint32_t r0 = 0u, r1 = (uint32_t)j;
      tf2x32(k0, k1, r0, r1);
      uint32_t word = __ballot_sync(0xffffffffu, ((r0 ^ r1) >> 31) == 0u);
      if ((tid & 31) == 0) g_updbits[s * (NPIX / 32) + (j >> 5)] = word;
    }
    return;
  }
  // ---- precompute: blocks (x<8, y==64) ----
  int b = blockIdx.x;
  if (b >= NB) return;
  // reset neighbor-sync flags every launch (graph-replay determinism)
  for (int i = b * 256 + tid; i < NBLK * 32; i += NB * 256) g_flagpad[i] = 0u;
  if (tid >= HID) return;
  int n = tid;
  const float* w1row = W1 + n * W1COLS;

  if (b == 0) {
    #pragma unroll
    for (int k = 0; k < 16; k++) g_Wz[k * HID + n] = w1row[k];
    #pragma unroll
    for (int c = 0; c < 16; c++)
      g_Wz[(16 + c) * HID + n] = w1row[16 + 2 * c] + w1row[17 + 2 * c];
    if (!(n & 1)) {
      int p = n >> 1;
      #pragma unroll
      for (int c = 0; c < 16; c++)
        g_W2p[p * 16 + c] = pack2(W2[c * HID + n], W2[c * HID + n + 1]);
    }
  }

  const float* wb = w + b * 128;
  float a0 = b1[n], a1 = 0.f, a2 = 0.f, a3 = 0.f;
  #pragma unroll
  for (int k = 0; k < 128; k += 4) {
    a0 = fmaf(w1row[48 + k],     __ldg(wb + k),     a0);
    a1 = fmaf(w1row[48 + k + 1], __ldg(wb + k + 1), a1);
    a2 = fmaf(w1row[48 + k + 2], __ldg(wb + k + 2), a2);
    a3 = fmaf(w1row[48 + k + 3], __ldg(wb + k + 3), a3);
  }
  float acc = (a0 + a1) + (a2 + a3);
  float accn1 = __shfl_down_sync(0xffffffffu, acc, 1);
  if (!(n & 1)) g_biasP[b * 64 + (n >> 1)] = pack2(acc, accn1);
}

// ---------------- Persistent fused NCA kernel (neighbor-flag sync) ----------------
__global__ void __launch_bounds__(256)
nca_persist(const float* __restrict__ xext, float* __restrict__ dout) {
  extern __shared__ __align__(16) unsigned char dyn[];
  float* sWz = (float*)(dyn + SM_WZ);
  ull* sW2p  = (ull*)(dyn + SM_W2);
  ull* sbias = (ull*)(dyn + SM_BI);
  float* smx = (float*)(dyn + SM_MX);
  float* salive = (float*)(dyn + SM_AL);
  float* salpha2 = (float*)(dyn + SM_A2);

  int tid = threadIdx.x;
  int blk = blockIdx.x;
  int b = blk / 18;
  int t = blk - b * 18;
  int tcx = t % 3, tcy = t / 3;
  int tx0 = tcx * TIW;
  int ty0 = tcy * TIH;

  // ---- neighbor list (batch-local, <=8) ----
  int nnb[8];
  int nn = 0;
  #pragma unroll
  for (int dy = -1; dy <= 1; dy++)
    #pragma unroll
    for (int dx = -1; dx <= 1; dx++) {
      if (dx == 0 && dy == 0) continue;
      int ncx = tcx + dx, ncy = tcy + dy;
      if (ncx >= 0 && ncx < 3 && ncy >= 0 && ncy < 6)
        nnb[nn++] = (b * 18 + ncy * 3 + ncx) * 32;
    }
  int myflag = blk * 32;

  // ---- load weights once ----
  {
    const float4* g1 = (const float4*)g_Wz;
    float4* s1 = (float4*)sWz;
    #pragma unroll
    for (int i = tid; i < 32 * HID / 4; i += 256) s1[i] = g1[i];
    const float4* g2 = (const float4*)g_W2p;
    float4* s2 = (float4*)sW2p;
    #pragma unroll
    for (int i = tid; i < 512; i += 256) s2[i] = g2[i];
    if (tid < 64) sbias[tid] = g_biasP[b * 64 + tid];
  }

  // ---- slots: halo1 (612 cells, w=34): 3/thread; halo2 (720 cells, w=36): 3/thread ----
  int fofs[3], sly[3], slx[3];
  bool fin[3], fvalid[3];
  #pragma unroll
  for (int i = 0; i < 3; i++) {
    int r = tid + i * 256;
    int ly = r / HLW, lx = r - (r / HLW) * HLW;
    int gy = ty0 + ly - 1, gx = tx0 + lx - 1;
    sly[i] = ly; slx[i] = lx;
    fvalid[i] = r < TSZ;
    fin[i] = fvalid[i] && ((unsigned)gy < 96u) && ((unsigned)gx < 96u);
    fofs[i] = gy * WW + gx;
  }
  int aofs[3];
  bool ain[3], avalid[3];
  #pragma unroll
  for (int i = 0; i < 3; i++) {
    int r = tid + i * 256;
    int ay = r / H2W, ax = r - (r / H2W) * H2W;
    int gy = ty0 + ay - 2, gx = tx0 + ax - 2;
    avalid[i] = r < H2SZ;
    ain[i] = avalid[i] && ((unsigned)gy < 96u) && ((unsigned)gx < 96u);
    aofs[i] = gy * WW + gx;
  }

  // ---- pixel mapping: 2 x-adjacent px/thread ----
  int pyy = tid >> 4;
  int pxs = (tid & 15) * 2;
  int ctr = (pyy + 1) * HLW + pxs + 1;
  int gy = ty0 + pyy, gx = tx0 + pxs;
  int j0 = b * HW + gy * WW + gx;
  int sh = j0 & 31;

  for (int s = 0; s < NSTEPS; s++) {
    const float* __restrict__ Rin = g_R[(s + 1) & 1] + b * CHW;
    const unsigned char* __restrict__ PLin = g_PL[(s + 1) & 1] + b * HW;

    if (s == 0) {
      const float* xb = xext + b * CHW;
      #pragma unroll 1
      for (int c = 0; c < 16; c++) {
        const float* src = xb + c * HW;
        #pragma unroll
        for (int i = 0; i < 3; i++) {
          int r = tid + i * 256;
          if (fvalid[i]) {
            float v = fin[i] ? __ldg(src + fofs[i]) : 0.f;
            smx[c * TSZ + r] = v;
            if (c == 3) salive[r] = fin[i] ? v : -1e30f;
          }
        }
      }
    } else {
      // ---- wait for <=8 neighbors to finish step s-1 ----
      if (tid < nn) {
        while (*(volatile unsigned*)&g_flagpad[nnb[tid]] < (unsigned)s) { }
        __threadfence();
      }
      __syncthreads();
      // ---- phase A: ONE batched round trip (alpha2 + PL + 15 channels) ----
      #pragma unroll
      for (int i = 0; i < 3; i++) {
        int r = tid + i * 256;
        if (avalid[i])
          salpha2[r] = ain[i] ? __ldcg(Rin + 3 * HW + aofs[i]) : -1e30f;
      }
      unsigned char plr[3];
      #pragma unroll
      for (int i = 0; i < 3; i++)
        plr[i] = fin[i] ? __ldcg(PLin + fofs[i]) : 0;
      float st[3][16];
      #pragma unroll
      for (int i = 0; i < 3; i++) {
        if (fvalid[i]) {
          #pragma unroll
          for (int c = 0; c < 16; c++)
            if (c != 3) st[i][c] = fin[i] ? __ldcg(Rin + c * HW + fofs[i]) : 0.f;
        }
      }
      __syncthreads();
      // ---- phase B: life mask locally, write masked tile ----
      #pragma unroll
      for (int i = 0; i < 3; i++) {
        int r = tid + i * 256;
        if (fvalid[i]) {
          float m = -1e30f;
          #pragma unroll
          for (int dy = 0; dy < 3; dy++) {
            const float* row = salpha2 + (sly[i] + dy) * H2W + slx[i];
            m = fmaxf(m, fmaxf(fmaxf(row[0], row[1]), row[2]));
          }
          float a3raw = salpha2[(sly[i] + 1) * H2W + slx[i] + 1];
          float sc = (fin[i] && m > 0.1f && plr[i]) ? 1.f : 0.f;
          #pragma unroll
          for (int c = 0; c < 16; c++)
            smx[c * TSZ + r] = (c == 3 ? a3raw : st[i][c]) * sc;
          salive[r] = fin[i] ? a3raw * sc : -1e30f;
        }
      }
    }
    __syncthreads();

    // ---- stencil: raw + sobel for both pixels ----
    float za[32], zb[32];
    #pragma unroll
    for (int c = 0; c < 16; c++) {
      const float* a = smx + c * TSZ;
      float tu0 = a[ctr - HLW - 1], tu1 = a[ctr - HLW], tu2 = a[ctr - HLW + 1], tu3 = a[ctr - HLW + 2];
      float tc0 = a[ctr - 1],       tc1 = a[ctr],       tc2 = a[ctr + 1],       tc3 = a[ctr + 2];
      float td0 = a[ctr + HLW - 1], td1 = a[ctr + HLW], td2 = a[ctr + HLW + 1], td3 = a[ctr + HLW + 2];
      za[c] = tc1; zb[c] = tc2;
      if (c < 8) {
        za[16 + c] = (tu2 - tu0) + 2.f * (tc2 - tc0) + (td2 - td0);
        zb[16 + c] = (tu3 - tu1) + 2.f * (tc3 - tc1) + (td3 - td1);
      } else {
        za[16 + c] = (td0 - tu0) + 2.f * (td1 - tu1) + (td2 - tu2);
        zb[16 + c] = (td1 - tu1) + 2.f * (td2 - tu2) + (td3 - tu3);
      }
    }

    // pre_life: 3x3 max over masked alpha (-inf OOB)
    float m0, m1;
    {
      const float* al = salive;
      float au0 = al[ctr - HLW - 1], au1 = al[ctr - HLW], au2 = al[ctr - HLW + 1], au3 = al[ctr - HLW + 2];
      float ac0 = al[ctr - 1],       ac1 = al[ctr],       ac2 = al[ctr + 1],       ac3 = al[ctr + 2];
      float ad0 = al[ctr + HLW - 1], ad1 = al[ctr + HLW], ad2 = al[ctr + HLW + 1], ad3 = al[ctr + HLW + 2];
      float mid = fmaxf(fmaxf(au1, au2), fmaxf(fmaxf(ac1, ac2), fmaxf(ad1, ad2)));
      m0 = fmaxf(mid, fmaxf(au0, fmaxf(ac0, ad0)));
      m1 = fmaxf(mid, fmaxf(au3, fmaxf(ac3, ad3)));
    }

    // ---- MLP: shared weight loads feed both pixels ----
    ull acc2a[16], acc2b[16];
    #pragma unroll
    for (int i = 0; i < 16; i++) { acc2a[i] = 0ull; acc2b[i] = 0ull; }

    #pragma unroll 1
    for (int gc = 0; gc < 8; gc++) {
      ull ha[8], hb[8];
      {
        const ulonglong2* bb = (const ulonglong2*)(sbias + gc * 8);
        #pragma unroll
        for (int i = 0; i < 4; i++) {
          ulonglong2 v = bb[i];
          ha[2 * i] = v.x; ha[2 * i + 1] = v.y;
          hb[2 * i] = v.x; hb[2 * i + 1] = v.y;
        }
      }
      #pragma unroll
      for (int k = 0; k < 32; k++) {
        ull wza = pack2(za[k], za[k]);
        ull wzb = pack2(zb[k], zb[k]);
        const ulonglong2* wv = (const ulonglong2*)(sWz + k * HID + gc * 16);
        #pragma unroll
        for (int i = 0; i < 4; i++) {
          ulonglong2 v = wv[i];
          ha[2 * i]     = fma2(wza, v.x, ha[2 * i]);
          ha[2 * i + 1] = fma2(wza, v.y, ha[2 * i + 1]);
          hb[2 * i]     = fma2(wzb, v.x, hb[2 * i]);
          hb[2 * i + 1] = fma2(wzb, v.y, hb[2 * i + 1]);
        }
      }
      #pragma unroll
      for (int pp = 0; pp < 8; pp++) {
        float2 fa = unpack2(ha[pp]);
        float2 fb = unpack2(hb[pp]);
        ull hra = pack2(fmaxf(fa.x, 0.f), fmaxf(fa.y, 0.f));
        ull hrb = pack2(fmaxf(fb.x, 0.f), fmaxf(fb.y, 0.f));
        const ulonglong2* w2 = (const ulonglong2*)(sW2p + (gc * 8 + pp) * 16);
        #pragma unroll
        for (int q = 0; q < 8; q++) {
          ulonglong2 v = w2[q];
          acc2a[2 * q]     = fma2(hra, v.x, acc2a[2 * q]);
          acc2a[2 * q + 1] = fma2(hra, v.y, acc2a[2 * q + 1]);
          acc2b[2 * q]     = fma2(hrb, v.x, acc2b[2 * q]);
          acc2b[2 * q + 1] = fma2(hrb, v.y, acc2b[2 * q + 1]);
        }
      }
    }

    // ---- stochastic gate + state write ----
    uint32_t wbits = __ldg(g_updbits + s * (NPIX / 32) + (j0 >> 5));
    float u0 = (((wbits >> sh) & 1u) && za[3] > 0.1f) ? 1.f : 0.f;
    float u1 = (((wbits >> (sh + 1)) & 1u) && zb[3] > 0.1f) ? 1.f : 0.f;

    float* Rout = g_R[s & 1] + b * CHW + gy * WW + gx;
    #pragma unroll
    for (int c = 0; c < 16; c++) {
      float2 da = unpack2(acc2a[c]);
      float2 db = unpack2(acc2b[c]);
      float2 o;
      o.x = fmaf(da.x + da.y, u0, za[c]);
      o.y = fmaf(db.x + db.y, u1, zb[c]);
      __stcg((float2*)(Rout + c * HW), o);
    }
    {
      unsigned short pl = (unsigned short)((m0 > 0.1f ? 1u : 0u) | ((m1 > 0.1f ? 1u : 0u) << 8));
      __stcg((unsigned short*)(g_PL[s & 1] + j0), pl);
    }

    __syncthreads();
    if (tid == 0) {
      __threadfence();
      *(volatile unsigned*)&g_flagpad[myflag] = (unsigned)(s + 1);
    }
  }

  // ---- final alive masking -> d_out ----
  {
    const float* __restrict__ Rin = g_R[(NSTEPS - 1) & 1] + b * CHW;
    const unsigned char* __restrict__ PLin = g_PL[(NSTEPS - 1) & 1] + b * HW;
    if (tid < nn) {
      while (*(volatile unsigned*)&g_flagpad[nnb[tid]] < (unsigned)NSTEPS) { }
      __threadfence();
    }
    __syncthreads();
    #pragma unroll
    for (int i = 0; i < 3; i++) {
      int r = tid + i * 256;
      if (avalid[i])
        salpha2[r] = ain[i] ? __ldcg(Rin + 3 * HW + aofs[i]) : -1e30f;
    }
    unsigned char plr[3];
    #pragma unroll
    for (int i = 0; i < 3; i++)
      plr[i] = fin[i] ? __ldcg(PLin + fofs[i]) : 0;
    float st[3][16];
    #pragma unroll
    for (int i = 0; i < 3; i++) {
      if (fvalid[i]) {
        #pragma unroll
        for (int c = 0; c < 16; c++)
          if (c != 3) st[i][c] = fin[i] ? __ldcg(Rin + c * HW + fofs[i]) : 0.f;
      }
    }
    __syncthreads();
    #pragma unroll
    for (int i = 0; i < 3; i++) {
      int r = tid + i * 256;
      if (fvalid[i]) {
        float m = -1e30f;
        #pragma unroll
        for (int dy = 0; dy < 3; dy++) {
          const float* row = salpha2 + (sly[i] + dy) * H2W + slx[i];
          m = fmaxf(m, fmaxf(fmaxf(row[0], row[1]), row[2]));
        }
        float a3raw = salpha2[(sly[i] + 1) * H2W + slx[i] + 1];
        float sc = (fin[i] && m > 0.1f && plr[i]) ? 1.f : 0.f;
        #pragma unroll
        for (int c = 0; c < 16; c++)
          smx[c * TSZ + r] = (c == 3 ? a3raw : st[i][c]) * sc;
      }
    }
    __syncthreads();

    float* ob = dout + b * CHW + gy * WW + gx;
    #pragma unroll
    for (int c = 0; c < 16; c++) {
      float2 v;
      v.x = smx[c * TSZ + ctr];
      v.y = smx[c * TSZ + ctr + 1];
      *(float2*)(ob + c * HW) = v;
    }
  }
}

// ---------------- Host ----------------
extern "C" void kernel_launch(void* const* d_in, const int* in_sizes, int n_in,
                              void* d_out, int out_size) {
  (void)in_sizes; (void)n_in; (void)out_size;
  const float* x  = (const float*)d_in[0];
  const float* w  = (const float*)d_in[1];
  const float* W1 = (const float*)d_in[3];
  const float* b1 = (const float*)d_in[4];
  const float* W2 = (const float*)d_in[5];

  cudaFuncSetAttribute(nca_persist, cudaFuncAttributeMaxDynamicSharedMemorySize, SM_TOT);

  init_kernel<<<dim3(72, NSTEPS + 1), 256>>>(W1, b1, W2, w);
  nca_persist<<<NBLK, 256, SM_TOT>>>(x, (float*)d_out);
}